// round 2
// baseline (speedup 1.0000x reference)
#include <cuda_runtime.h>
#include <cuda_bf16.h>

#define N_NODES 50000
#define N_EDGES 800000
#define D 128

// Scratch (allocation-free rule: __device__ globals)
__device__ __align__(16) float g_agg[N_NODES * D];   // 25.6 MB
__device__ __align__(16) float g_deg[N_NODES];

// ---------------------------------------------------------------------------
// Kernel 1: zero the accumulation scratch (graph replays require re-zeroing)
// ---------------------------------------------------------------------------
__global__ void zero_kernel() {
    int i = blockIdx.x * blockDim.x + threadIdx.x;
    const int n4 = (N_NODES * D) / 4;   // 1,600,000 float4s
    if (i < n4) {
        ((float4*)g_agg)[i] = make_float4(0.f, 0.f, 0.f, 0.f);
    }
    if (i < N_NODES) {
        g_deg[i] = 0.f;
    }
}

// ---------------------------------------------------------------------------
// Kernel 2: edge scatter. One warp per edge; each lane moves a float4 of the
// source row into the destination row via vector reduction (red.global.v4).
// edge_index is int32 (JAX x64-disabled downcasts the requested int64).
// ---------------------------------------------------------------------------
__device__ __forceinline__ void red_add_v4(float* addr, float4 v) {
    asm volatile("red.global.add.v4.f32 [%0], {%1, %2, %3, %4};"
                 :: "l"(addr), "f"(v.x), "f"(v.y), "f"(v.z), "f"(v.w)
                 : "memory");
}

__global__ void __launch_bounds__(256) scatter_kernel(
    const float* __restrict__ x,
    const int* __restrict__ ei)   // [2, E] int32: src row then dst row
{
    unsigned tid = blockIdx.x * blockDim.x + threadIdx.x;
    unsigned e = tid >> 5;
    unsigned lane = tid & 31;
    if (e >= N_EDGES) return;

    int src = ei[e];
    int dst = ei[N_EDGES + e];
    // Defensive: if dtype assumption is ever wrong, fail soft (rel_err),
    // not with an illegal access.
    if ((unsigned)src >= N_NODES || (unsigned)dst >= N_NODES) return;

    float4 v = *(const float4*)(x + (size_t)src * D + lane * 4);
    red_add_v4(g_agg + (size_t)dst * D + lane * 4, v);

    if (lane == 0) {
        atomicAdd(&g_deg[dst], 1.0f);
    }
}

// ---------------------------------------------------------------------------
// Kernel 3: fused  out = relu( (agg/deg) @ W_l^T + b_l + x @ W_r^T )
// Tiled as [TN=64 nodes] x [128 cols] per 256-thread block.
// Wsm holds the concatenated transposed weight [k=0..255][c=0..127],
// row stride 132 floats (16B-aligned rows, reduces STS bank conflicts).
// ---------------------------------------------------------------------------
#define TN 64
#define WSTR 132
#define SMEM_FLOATS (256 * WSTR + TN * 256 + TN)
#define SMEM_BYTES  (SMEM_FLOATS * 4)

__global__ void __launch_bounds__(256) sage_gemm(
    const float* __restrict__ x,
    const float* __restrict__ W_l,
    const float* __restrict__ b_l,
    const float* __restrict__ W_r,
    float* __restrict__ out)
{
    extern __shared__ float sm[];
    float* Wsm  = sm;                    // 256 x WSTR
    float* insm = sm + 256 * WSTR;       // TN x 256
    float* ssm  = insm + TN * 256;       // TN

    const int t = threadIdx.x;
    const int nodeBase = blockIdx.x * TN;

    // Load W_l / W_r transposed into Wsm: Wsm[k][c] = W[c][k]
    #pragma unroll 4
    for (int l = t; l < D * D; l += 256) {
        int c = l >> 7;
        int k = l & 127;
        float wl = W_l[l];
        float wr = W_r[l];
        Wsm[k * WSTR + c]        = wl;
        Wsm[(k + 128) * WSTR + c] = wr;
    }

    // Per-node 1/max(deg,1)
    if (t < TN) {
        int n = nodeBase + t;
        float dg = (n < N_NODES) ? g_deg[n] : 1.0f;
        ssm[t] = 1.0f / fmaxf(dg, 1.0f);
    }
    __syncthreads();

    // Load input tile: insm[node][k] = (k<128 ? agg[n][k]*s : x[n][k-128])
    for (int l = t; l < TN * 256; l += 256) {
        int node = l >> 8;
        int k = l & 255;
        int n = nodeBase + node;
        float v = 0.0f;
        if (n < N_NODES) {
            if (k < 128) v = g_agg[(size_t)n * D + k] * ssm[node];
            else         v = x[(size_t)n * D + (k - 128)];
        }
        insm[l] = v;
    }
    __syncthreads();

    const int c0 = (t & 31) * 4;   // output column group (per lane)
    const int n0 = (t >> 5) * 8;   // node group (per warp)

    float acc[8][4];
    #pragma unroll
    for (int i = 0; i < 8; i++)
        #pragma unroll
        for (int j = 0; j < 4; j++) acc[i][j] = 0.f;

    #pragma unroll 2
    for (int k = 0; k < 256; k++) {
        float4 w = *(const float4*)&Wsm[k * WSTR + c0];
        #pragma unroll
        for (int i = 0; i < 8; i++) {
            float a = insm[(n0 + i) * 256 + k];
            acc[i][0] = fmaf(a, w.x, acc[i][0]);
            acc[i][1] = fmaf(a, w.y, acc[i][1]);
            acc[i][2] = fmaf(a, w.z, acc[i][2]);
            acc[i][3] = fmaf(a, w.w, acc[i][3]);
        }
    }

    float4 bias = *(const float4*)&b_l[c0];
    #pragma unroll
    for (int i = 0; i < 8; i++) {
        int n = nodeBase + n0 + i;
        if (n < N_NODES) {
            float4 o;
            o.x = fmaxf(acc[i][0] + bias.x, 0.f);
            o.y = fmaxf(acc[i][1] + bias.y, 0.f);
            o.z = fmaxf(acc[i][2] + bias.z, 0.f);
            o.w = fmaxf(acc[i][3] + bias.w, 0.f);
            *(float4*)&out[(size_t)n * D + c0] = o;
        }
    }
}

// ---------------------------------------------------------------------------
extern "C" void kernel_launch(void* const* d_in, const int* in_sizes, int n_in,
                              void* d_out, int out_size) {
    const float* x   = (const float*)d_in[0];
    const int*   ei  = (const int*)d_in[1];
    const float* W_l = (const float*)d_in[2];
    const float* b_l = (const float*)d_in[3];
    const float* W_r = (const float*)d_in[4];
    float*       out = (float*)d_out;

    cudaFuncSetAttribute(sage_gemm,
                         cudaFuncAttributeMaxDynamicSharedMemorySize,
                         SMEM_BYTES);

    // zero scratch: 1,600,000 float4 slots -> 6250 blocks of 256
    zero_kernel<<<6250, 256>>>();

    // one warp per edge: 800000 * 32 / 256 = 100000 blocks
    scatter_kernel<<<100000, 256>>>(x, ei);

    // 50000 / 64 = 781.25 -> 782 blocks
    sage_gemm<<<(N_NODES + TN - 1) / TN, 256, SMEM_BYTES>>>(x, W_l, b_l, W_r, out);
}